// round 1
// baseline (speedup 1.0000x reference)
#include <cuda_runtime.h>
#include <cuda_bf16.h>
#include <math_constants.h>

// Problem dims (fixed by the dataset)
constexpr int Bn = 2;
constexpr int Sn = 2048;
constexpr int Dn = 1024;
constexpr int Hn = 16;
constexpr int An = 64;
constexpr int Mrows = Bn * Sn;        // 4096
constexpr int HA = Hn * An;           // 1024

// Scratch (device globals; allocation-free)
__device__ float g_q[(size_t)Bn * Hn * Sn * An];   // [B,H,S,A]
__device__ float g_k[(size_t)Bn * Hn * Sn * An];
__device__ float g_v[(size_t)Bn * Hn * Sn * An];
__device__ float g_z[(size_t)Bn * Sn * Hn * An];   // [B,S,H,A]

// ---------------------------------------------------------------------------
// QKV projection GEMM: out[b,h,s,a] = sum_d X[b,s,d] * W[h,d,a] + bias[h,a]
// X: [4096,1024] row-major. Treated as GEMM M=4096, N=1024 (n = h*64+a), K=1024.
// grid = (N/128, M/128, 3); z selects Wq/Wk/Wv -> g_q/g_k/g_v
// ---------------------------------------------------------------------------
__global__ __launch_bounds__(256) void gemm_qkv_kernel(
    const float* __restrict__ X,
    const float* __restrict__ Wq, const float* __restrict__ Wk, const float* __restrict__ Wv,
    const float* __restrict__ bq, const float* __restrict__ bk, const float* __restrict__ bv)
{
    __shared__ float As[8][128];
    __shared__ float Bs[8][128];

    const int tid = threadIdx.x;
    const int tx = tid & 15;
    const int ty = tid >> 4;
    const int m0 = blockIdx.y * 128;
    const int n0 = blockIdx.x * 128;

    const float* W;
    const float* bias;
    float* O;
    if (blockIdx.z == 0)      { W = Wq; bias = bq; O = g_q; }
    else if (blockIdx.z == 1) { W = Wk; bias = bk; O = g_k; }
    else                      { W = Wv; bias = bv; O = g_v; }

    float acc[8][8];
    #pragma unroll
    for (int i = 0; i < 8; i++)
        #pragma unroll
        for (int j = 0; j < 8; j++) acc[i][j] = 0.0f;

    const int arow = tid >> 1;          // 0..127
    const int akq  = (tid & 1) * 4;     // 0 or 4
    const int brow = tid >> 5;          // 0..7
    const int bnq  = (tid & 31) * 4;    // 0..124

    for (int kt = 0; kt < Dn; kt += 8) {
        // A tile: 128 rows x 8 k, stored transposed
        float4 va = *(const float4*)&X[(size_t)(m0 + arow) * Dn + kt + akq];
        As[akq + 0][arow] = va.x;
        As[akq + 1][arow] = va.y;
        As[akq + 2][arow] = va.z;
        As[akq + 3][arow] = va.w;
        // B tile: 8 k x 128 n ; W element (k, n) = W[(n>>6)*D*A + k*A + (n&63)]
        {
            int n = n0 + bnq;
            float4 vb = *(const float4*)&W[(size_t)(n >> 6) * (Dn * An)
                                           + (size_t)(kt + brow) * An + (n & 63)];
            *(float4*)&Bs[brow][bnq] = vb;
        }
        __syncthreads();
        #pragma unroll
        for (int k = 0; k < 8; ++k) {
            float ar[8], br[8];
            float4 a0 = *(const float4*)&As[k][ty * 8];
            float4 a1 = *(const float4*)&As[k][ty * 8 + 4];
            ar[0] = a0.x; ar[1] = a0.y; ar[2] = a0.z; ar[3] = a0.w;
            ar[4] = a1.x; ar[5] = a1.y; ar[6] = a1.z; ar[7] = a1.w;
            #pragma unroll
            for (int j = 0; j < 8; ++j) br[j] = Bs[k][tx + 16 * j];
            #pragma unroll
            for (int i = 0; i < 8; ++i)
                #pragma unroll
                for (int j = 0; j < 8; ++j)
                    acc[i][j] = fmaf(ar[i], br[j], acc[i][j]);
        }
        __syncthreads();
    }

    // Epilogue: write to [B,H,S,A]
    #pragma unroll
    for (int i = 0; i < 8; ++i) {
        int mm = m0 + ty * 8 + i;
        int b = mm >> 11;          // /2048
        int s = mm & 2047;
        #pragma unroll
        for (int j = 0; j < 8; ++j) {
            int nn = n0 + tx + 16 * j;
            int h = nn >> 6;
            int a = nn & 63;
            float v = acc[i][j] + bias[nn];
            O[(((size_t)b * Hn + h) * Sn + s) * An + a] = v;
        }
    }
}

// ---------------------------------------------------------------------------
// Output projection GEMM: out[bs, d] = sum_c z[bs, c] * Wo[c, d] + bo[d]
// Wo is [H,A,D] = contiguous [1024,1024] row-major (k=h*A+a rows, d cols).
// ---------------------------------------------------------------------------
__global__ __launch_bounds__(256) void gemm_out_kernel(
    const float* __restrict__ Wo, const float* __restrict__ bo,
    float* __restrict__ out)
{
    __shared__ float As[8][128];
    __shared__ float Bs[8][128];

    const int tid = threadIdx.x;
    const int tx = tid & 15;
    const int ty = tid >> 4;
    const int m0 = blockIdx.y * 128;
    const int n0 = blockIdx.x * 128;

    float acc[8][8];
    #pragma unroll
    for (int i = 0; i < 8; i++)
        #pragma unroll
        for (int j = 0; j < 8; j++) acc[i][j] = 0.0f;

    const int arow = tid >> 1;
    const int akq  = (tid & 1) * 4;
    const int brow = tid >> 5;
    const int bnq  = (tid & 31) * 4;

    const float* X = g_z;   // [4096, 1024]

    for (int kt = 0; kt < HA; kt += 8) {
        float4 va = *(const float4*)&X[(size_t)(m0 + arow) * HA + kt + akq];
        As[akq + 0][arow] = va.x;
        As[akq + 1][arow] = va.y;
        As[akq + 2][arow] = va.z;
        As[akq + 3][arow] = va.w;
        float4 vb = *(const float4*)&Wo[(size_t)(kt + brow) * Dn + n0 + bnq];
        *(float4*)&Bs[brow][bnq] = vb;
        __syncthreads();
        #pragma unroll
        for (int k = 0; k < 8; ++k) {
            float ar[8], br[8];
            float4 a0 = *(const float4*)&As[k][ty * 8];
            float4 a1 = *(const float4*)&As[k][ty * 8 + 4];
            ar[0] = a0.x; ar[1] = a0.y; ar[2] = a0.z; ar[3] = a0.w;
            ar[4] = a1.x; ar[5] = a1.y; ar[6] = a1.z; ar[7] = a1.w;
            #pragma unroll
            for (int j = 0; j < 8; ++j) br[j] = Bs[k][tx + 16 * j];
            #pragma unroll
            for (int i = 0; i < 8; ++i)
                #pragma unroll
                for (int j = 0; j < 8; ++j)
                    acc[i][j] = fmaf(ar[i], br[j], acc[i][j]);
        }
        __syncthreads();
    }

    #pragma unroll
    for (int i = 0; i < 8; ++i) {
        int mm = m0 + ty * 8 + i;
        #pragma unroll
        for (int j = 0; j < 8; ++j) {
            int nn = n0 + tx + 16 * j;
            out[(size_t)mm * Dn + nn] = acc[i][j] + bo[nn];
        }
    }
}

// ---------------------------------------------------------------------------
// Causal flash attention, fp32. BM=128 query rows per CTA, BN=64 kv per tile.
// grid = (S/128, B*H), 256 threads. thread (tx,ty): rows ty*8+{0..7},
// cols tx+16*{0..3}. Online softmax; P staged through SMEM for the P@V GEMM.
// Reference's -100000 mask == -inf (exp underflows to 0 in fp32).
// ---------------------------------------------------------------------------
constexpr int FLASH_SMEM_FLOATS = 128 * 68 + 64 * 68 + 64 * 68 + 128 * 68; // 26112
constexpr int FLASH_SMEM_BYTES = FLASH_SMEM_FLOATS * 4;                    // 104448

__global__ __launch_bounds__(256) void flash_kernel()
{
    extern __shared__ float sm[];
    float* sQ = sm;                    // [128][68]
    float* sK = sQ + 128 * 68;         // [64][68]
    float* sV = sK + 64 * 68;          // [64][68]
    float* sP = sV + 64 * 68;          // [128][68]

    const int tid = threadIdx.x;
    const int tx = tid & 15;
    const int ty = tid >> 4;
    const int bh = blockIdx.y;                 // b*H + h
    const size_t base = (size_t)bh * Sn * An;
    const int q0 = blockIdx.x * 128;

    // Load Q tile [128][64]
    for (int idx = tid; idx < 128 * 16; idx += 256) {
        int r = idx >> 4;
        int c4 = (idx & 15) * 4;
        *(float4*)&sQ[r * 68 + c4] = *(const float4*)&g_q[base + (size_t)(q0 + r) * An + c4];
    }

    float m_i[8], l_i[8], o[8][4];
    #pragma unroll
    for (int i = 0; i < 8; ++i) {
        m_i[i] = -1e30f;
        l_i[i] = 0.0f;
        #pragma unroll
        for (int j = 0; j < 4; ++j) o[i][j] = 0.0f;
    }

    for (int j0 = 0; j0 < q0 + 128; j0 += 64) {
        // Load K, V tiles [64][64]
        for (int idx = tid; idx < 64 * 16; idx += 256) {
            int r = idx >> 4;
            int c4 = (idx & 15) * 4;
            *(float4*)&sK[r * 68 + c4] = *(const float4*)&g_k[base + (size_t)(j0 + r) * An + c4];
            *(float4*)&sV[r * 68 + c4] = *(const float4*)&g_v[base + (size_t)(j0 + r) * An + c4];
        }
        __syncthreads();

        // S = Q @ K^T
        float sacc[8][4];
        #pragma unroll
        for (int i = 0; i < 8; ++i)
            #pragma unroll
            for (int j = 0; j < 4; ++j) sacc[i][j] = 0.0f;

        #pragma unroll 4
        for (int a4 = 0; a4 < 16; ++a4) {
            float qf[8][4], kf[4][4];
            #pragma unroll
            for (int i = 0; i < 8; ++i) {
                float4 t = *(const float4*)&sQ[(ty * 8 + i) * 68 + a4 * 4];
                qf[i][0] = t.x; qf[i][1] = t.y; qf[i][2] = t.z; qf[i][3] = t.w;
            }
            #pragma unroll
            for (int j = 0; j < 4; ++j) {
                float4 t = *(const float4*)&sK[(tx + 16 * j) * 68 + a4 * 4];
                kf[j][0] = t.x; kf[j][1] = t.y; kf[j][2] = t.z; kf[j][3] = t.w;
            }
            #pragma unroll
            for (int i = 0; i < 8; ++i)
                #pragma unroll
                for (int j = 0; j < 4; ++j)
                    #pragma unroll
                    for (int e = 0; e < 4; ++e)
                        sacc[i][j] = fmaf(qf[i][e], kf[j][e], sacc[i][j]);
        }

        const bool needmask = (j0 + 63 > q0);
        #pragma unroll
        for (int i = 0; i < 8; ++i) {
            #pragma unroll
            for (int j = 0; j < 4; ++j) {
                float sv = sacc[i][j] * 0.125f;   // 1/sqrt(64)
                if (needmask) {
                    int qi = q0 + ty * 8 + i;
                    int kj = j0 + tx + 16 * j;
                    if (kj > qi) sv = -1e30f;
                }
                sacc[i][j] = sv;
            }
        }

        // Online softmax per row (16 threads of same ty share a row; they are a half-warp)
        #pragma unroll
        for (int i = 0; i < 8; ++i) {
            float rm = fmaxf(fmaxf(sacc[i][0], sacc[i][1]), fmaxf(sacc[i][2], sacc[i][3]));
            #pragma unroll
            for (int d = 1; d < 16; d <<= 1)
                rm = fmaxf(rm, __shfl_xor_sync(0xffffffffu, rm, d));
            float mnew = fmaxf(m_i[i], rm);
            float corr = __expf(m_i[i] - mnew);
            float rs = 0.0f;
            #pragma unroll
            for (int j = 0; j < 4; ++j) {
                float p = __expf(sacc[i][j] - mnew);
                sP[(ty * 8 + i) * 68 + tx + 16 * j] = p;
                rs += p;
            }
            #pragma unroll
            for (int d = 1; d < 16; d <<= 1)
                rs += __shfl_xor_sync(0xffffffffu, rs, d);
            l_i[i] = l_i[i] * corr + rs;
            m_i[i] = mnew;
            #pragma unroll
            for (int j = 0; j < 4; ++j) o[i][j] *= corr;
        }
        __syncthreads();

        // O += P @ V
        #pragma unroll 2
        for (int c4 = 0; c4 < 16; ++c4) {
            float pf[8][4];
            #pragma unroll
            for (int i = 0; i < 8; ++i) {
                float4 t = *(const float4*)&sP[(ty * 8 + i) * 68 + c4 * 4];
                pf[i][0] = t.x; pf[i][1] = t.y; pf[i][2] = t.z; pf[i][3] = t.w;
            }
            #pragma unroll
            for (int cc = 0; cc < 4; ++cc) {
                float vv[4];
                #pragma unroll
                for (int j = 0; j < 4; ++j)
                    vv[j] = sV[(c4 * 4 + cc) * 68 + tx + 16 * j];
                #pragma unroll
                for (int i = 0; i < 8; ++i)
                    #pragma unroll
                    for (int j = 0; j < 4; ++j)
                        o[i][j] = fmaf(pf[i][cc], vv[j], o[i][j]);
            }
        }
        __syncthreads();
    }

    // Normalize and write z in [B,S,H,A]
    const int b = bh / Hn;
    const int h = bh % Hn;
    #pragma unroll
    for (int i = 0; i < 8; ++i) {
        float inv = 1.0f / l_i[i];
        int srow = q0 + ty * 8 + i;
        size_t zb = (((size_t)b * Sn + srow) * Hn + h) * (size_t)An;
        #pragma unroll
        for (int j = 0; j < 4; ++j)
            g_z[zb + tx + 16 * j] = o[i][j] * inv;
    }
}

// ---------------------------------------------------------------------------
extern "C" void kernel_launch(void* const* d_in, const int* in_sizes, int n_in,
                              void* d_out, int out_size)
{
    const float* residual = (const float*)d_in[0];
    const float* Wq = (const float*)d_in[1];
    const float* Wk = (const float*)d_in[2];
    const float* Wv = (const float*)d_in[3];
    const float* Wo = (const float*)d_in[4];
    const float* bq = (const float*)d_in[5];
    const float* bk = (const float*)d_in[6];
    const float* bv = (const float*)d_in[7];
    const float* bo = (const float*)d_in[8];
    float* out = (float*)d_out;

    // >48KB dynamic smem opt-in (persistent per-function state; idempotent)
    cudaFuncSetAttribute(flash_kernel,
                         cudaFuncAttributeMaxDynamicSharedMemorySize,
                         FLASH_SMEM_BYTES);

    // 1) QKV projections
    gemm_qkv_kernel<<<dim3(HA / 128, Mrows / 128, 3), 256>>>(
        residual, Wq, Wk, Wv, bq, bk, bv);

    // 2) Causal flash attention
    flash_kernel<<<dim3(Sn / 128, Bn * Hn), 256, FLASH_SMEM_BYTES>>>();

    // 3) Output projection
    gemm_out_kernel<<<dim3(Dn / 128, Mrows / 128), 256>>>(Wo, bo, out);
}

// round 4
// speedup vs baseline: 1.5955x; 1.5955x over previous
#include <cuda_runtime.h>
#include <cuda_bf16.h>
#include <cstdint>

// Problem dims (fixed)
constexpr int Bn = 2;
constexpr int Sn = 2048;
constexpr int Dn = 1024;
constexpr int Hn = 16;
constexpr int An = 64;
constexpr int Mrows = Bn * Sn;        // 4096
constexpr int HA = Hn * An;           // 1024

// Scratch (device globals; allocation-free)
__device__ __align__(256) float g_q[(size_t)Bn * Hn * Sn * An];   // [B,H,S,A]
__device__ __align__(256) float g_k[(size_t)Bn * Hn * Sn * An];
__device__ __align__(256) float g_v[(size_t)Bn * Hn * Sn * An];
__device__ __align__(256) float g_z[(size_t)Bn * Sn * Hn * An];   // [B,S,H,A]

// ---------------------------------------------------------------------------
// Helpers (sm_80-baseline PTX only: cp.async + mma.sync tf32; NO tcgen05)
// ---------------------------------------------------------------------------
__device__ __forceinline__ void cp_async16(uint32_t dst, const void* src) {
    asm volatile("cp.async.cg.shared.global [%0], [%1], 16;" :: "r"(dst), "l"(src) : "memory");
}
__device__ __forceinline__ uint32_t smem_u32(const void* p) {
    uint32_t a;
    asm("{ .reg .u64 t; cvta.to.shared.u64 t, %1; cvt.u32.u64 %0, t; }" : "=r"(a) : "l"(p));
    return a;
}
__device__ __forceinline__ void cp_commit() {
    asm volatile("cp.async.commit_group;" ::: "memory");
}
template <int N>
__device__ __forceinline__ void cp_wait() {
    asm volatile("cp.async.wait_group %0;" :: "n"(N) : "memory");
}
__device__ __forceinline__ uint32_t f2tf32(float x) {
    uint32_t r;
    asm("cvt.rna.tf32.f32 %0, %1;" : "=r"(r) : "f"(x));
    return r;
}
__device__ __forceinline__ void mma_tf32_16n8k8(float* c, const uint32_t* a, const uint32_t* b) {
    asm volatile(
        "mma.sync.aligned.m16n8k8.row.col.f32.tf32.tf32.f32 "
        "{%0,%1,%2,%3}, {%4,%5,%6,%7}, {%8,%9}, {%0,%1,%2,%3};"
        : "+f"(c[0]), "+f"(c[1]), "+f"(c[2]), "+f"(c[3])
        : "r"(a[0]), "r"(a[1]), "r"(a[2]), "r"(a[3]), "r"(b[0]), "r"(b[1]));
}

// ---------------------------------------------------------------------------
// tf32 mma.sync GEMM: C[M=4096, N=1024] = A[M,1024] x W(k-major) + bias
// MODE 0: QKV (z selects W/bias/output, heads layout). MODE 1: out projection,
//         A operand is the device-global g_z (NOT a host-passed pointer).
// BM=128, BN=128, BK=32, 256 threads (8 warps: 2 m x 4 n), warp tile 64x32.
// ---------------------------------------------------------------------------
constexpr int LDA = 36;    // floats per A smem row
constexpr int LDB = 136;   // floats per B smem row
constexpr int A_STG = 128 * LDA;            // floats
constexpr int B_STG = 32 * LDB;             // floats
constexpr int STG_FLOATS = A_STG + B_STG;   // 8960
constexpr int NSTAGE = 3;
constexpr int GEMM_SMEM = NSTAGE * STG_FLOATS * 4;   // 107520 bytes
constexpr int KCHUNKS = 1024 / 32;

template<int MODE>
__global__ __launch_bounds__(256) void gemm_mma_kernel(
    const float* __restrict__ Ain,
    const float* __restrict__ Wq, const float* __restrict__ Wk, const float* __restrict__ Wv,
    const float* __restrict__ b0, const float* __restrict__ b1, const float* __restrict__ b2,
    float* __restrict__ outp)
{
    extern __shared__ __align__(16) float smem[];

    const int tid = threadIdx.x;
    const int lane = tid & 31;
    const int wid = tid >> 5;
    const int warp_m = wid & 1;     // 0..1  (64 rows each)
    const int warp_n = wid >> 1;    // 0..3  (32 cols each)
    const int grp = lane >> 2;      // 0..7
    const int qd = lane & 3;        // 0..3

    const int m0 = blockIdx.y * 128;
    const int n0 = blockIdx.x * 128;
    const int z = blockIdx.z;

    // A operand: host input for MODE 0, device-global z for MODE 1.
    const float* A = (MODE == 0) ? Ain : (const float*)g_z;

    const float* W;
    const float* bias;
    if (MODE == 0) {
        W = (z == 0) ? Wq : (z == 1) ? Wk : Wv;     // [H][D][A] : k-major per head
        bias = (z == 0) ? b0 : (z == 1) ? b1 : b2;
    } else {
        W = Wq;                                     // Wo [HA][D] : k-major
        bias = b0;
    }

    const uint32_t smem_base = smem_u32(smem);

    // ---- producer: stage slot gets k-chunk kc ----
    auto produce = [&](int kc) {
        const int slot = kc % NSTAGE;
        const uint32_t sA = smem_base + (uint32_t)(slot * STG_FLOATS) * 4;
        const uint32_t sB = sA + (uint32_t)A_STG * 4;
        #pragma unroll
        for (int i = 0; i < 4; ++i) {
            int task = i * 256 + tid;
            int r = task >> 3;
            int sgm = task & 7;
            cp_async16(sA + (uint32_t)(r * LDA + sgm * 4) * 4,
                       A + (size_t)(m0 + r) * 1024 + kc * 32 + sgm * 4);
        }
        #pragma unroll
        for (int i = 0; i < 4; ++i) {
            int task = i * 256 + tid;
            int kr = task >> 5;
            int sgm = task & 31;
            int nl = sgm * 4;
            const float* src;
            if (MODE == 0) {
                int ng = n0 + nl;
                src = W + (size_t)(ng >> 6) * (Dn * An) + (size_t)(kc * 32 + kr) * An + (ng & 63);
            } else {
                src = W + (size_t)(kc * 32 + kr) * Dn + n0 + nl;
            }
            cp_async16(sB + (uint32_t)(kr * LDB + nl) * 4, src);
        }
        cp_commit();
    };

    float acc[4][4][4];
    #pragma unroll
    for (int mt = 0; mt < 4; ++mt)
        #pragma unroll
        for (int nt = 0; nt < 4; ++nt)
            #pragma unroll
            for (int e = 0; e < 4; ++e) acc[mt][nt][e] = 0.0f;

    produce(0);
    produce(1);

    for (int kc = 0; kc < KCHUNKS; ++kc) {
        cp_wait<1>();            // this thread's chunk-kc copies resident
        __syncthreads();         // all threads' copies resident
        if (kc + 2 < KCHUNKS) produce(kc + 2);

        const int slot = kc % NSTAGE;
        const float* sA = smem + slot * STG_FLOATS;
        const float* sB = sA + A_STG;

        #pragma unroll
        for (int ks = 0; ks < 4; ++ks) {
            uint32_t af[4][4], bf[4][2];
            #pragma unroll
            for (int mt = 0; mt < 4; ++mt) {
                const int rb = warp_m * 64 + mt * 16 + grp;
                const int cb = ks * 8 + qd;
                af[mt][0] = f2tf32(sA[rb * LDA + cb]);
                af[mt][1] = f2tf32(sA[(rb + 8) * LDA + cb]);
                af[mt][2] = f2tf32(sA[rb * LDA + cb + 4]);
                af[mt][3] = f2tf32(sA[(rb + 8) * LDA + cb + 4]);
            }
            #pragma unroll
            for (int nt = 0; nt < 4; ++nt) {
                const int nb = warp_n * 32 + nt * 8 + grp;
                bf[nt][0] = f2tf32(sB[(ks * 8 + qd) * LDB + nb]);
                bf[nt][1] = f2tf32(sB[(ks * 8 + qd + 4) * LDB + nb]);
            }
            #pragma unroll
            for (int mt = 0; mt < 4; ++mt)
                #pragma unroll
                for (int nt = 0; nt < 4; ++nt)
                    mma_tf32_16n8k8(acc[mt][nt], af[mt], bf[nt]);
        }
        __syncthreads();         // stage fully consumed before overwrite
    }

    // ---- epilogue ----
    #pragma unroll
    for (int mt = 0; mt < 4; ++mt) {
        #pragma unroll
        for (int half = 0; half < 2; ++half) {
            const int m = m0 + warp_m * 64 + mt * 16 + grp + half * 8;
            #pragma unroll
            for (int nt = 0; nt < 4; ++nt) {
                const int n = n0 + warp_n * 32 + nt * 8 + qd * 2;
                float2 v;
                v.x = acc[mt][nt][half * 2 + 0] + bias[n];
                v.y = acc[mt][nt][half * 2 + 1] + bias[n + 1];
                if (MODE == 0) {
                    const int b = m >> 11;
                    const int s = m & 2047;
                    float* O = (z == 0) ? g_q : (z == 1) ? g_k : g_v;
                    *(float2*)&O[(((size_t)b * Hn + (n >> 6)) * Sn + s) * An + (n & 63)] = v;
                } else {
                    *(float2*)&outp[(size_t)m * Dn + n] = v;
                }
            }
        }
    }
}

// ---------------------------------------------------------------------------
// Causal flash attention, fp32 SIMT (unchanged, proven in R1)
// ---------------------------------------------------------------------------
constexpr int FLASH_SMEM_FLOATS = 128 * 68 + 64 * 68 + 64 * 68 + 128 * 68;
constexpr int FLASH_SMEM_BYTES = FLASH_SMEM_FLOATS * 4;

__global__ __launch_bounds__(256) void flash_kernel()
{
    extern __shared__ float sm[];
    float* sQ = sm;
    float* sK = sQ + 128 * 68;
    float* sV = sK + 64 * 68;
    float* sP = sV + 64 * 68;

    const int tid = threadIdx.x;
    const int tx = tid & 15;
    const int ty = tid >> 4;
    const int bh = blockIdx.y;
    const size_t base = (size_t)bh * Sn * An;
    const int q0 = blockIdx.x * 128;

    for (int idx = tid; idx < 128 * 16; idx += 256) {
        int r = idx >> 4;
        int c4 = (idx & 15) * 4;
        *(float4*)&sQ[r * 68 + c4] = *(const float4*)&g_q[base + (size_t)(q0 + r) * An + c4];
    }

    float m_i[8], l_i[8], o[8][4];
    #pragma unroll
    for (int i = 0; i < 8; ++i) {
        m_i[i] = -1e30f;
        l_i[i] = 0.0f;
        #pragma unroll
        for (int j = 0; j < 4; ++j) o[i][j] = 0.0f;
    }

    for (int j0 = 0; j0 < q0 + 128; j0 += 64) {
        for (int idx = tid; idx < 64 * 16; idx += 256) {
            int r = idx >> 4;
            int c4 = (idx & 15) * 4;
            *(float4*)&sK[r * 68 + c4] = *(const float4*)&g_k[base + (size_t)(j0 + r) * An + c4];
            *(float4*)&sV[r * 68 + c4] = *(const float4*)&g_v[base + (size_t)(j0 + r) * An + c4];
        }
        __syncthreads();

        float sacc[8][4];
        #pragma unroll
        for (int i = 0; i < 8; ++i)
            #pragma unroll
            for (int j = 0; j < 4; ++j) sacc[i][j] = 0.0f;

        #pragma unroll 4
        for (int a4 = 0; a4 < 16; ++a4) {
            float qf[8][4], kf[4][4];
            #pragma unroll
            for (int i = 0; i < 8; ++i) {
                float4 t = *(const float4*)&sQ[(ty * 8 + i) * 68 + a4 * 4];
                qf[i][0] = t.x; qf[i][1] = t.y; qf[i][2] = t.z; qf[i][3] = t.w;
            }
            #pragma unroll
            for (int j = 0; j < 4; ++j) {
                float4 t = *(const float4*)&sK[(tx + 16 * j) * 68 + a4 * 4];
                kf[j][0] = t.x; kf[j][1] = t.y; kf[j][2] = t.z; kf[j][3] = t.w;
            }
            #pragma unroll
            for (int i = 0; i < 8; ++i)
                #pragma unroll
                for (int j = 0; j < 4; ++j)
                    #pragma unroll
                    for (int e = 0; e < 4; ++e)
                        sacc[i][j] = fmaf(qf[i][e], kf[j][e], sacc[i][j]);
        }

        const bool needmask = (j0 + 63 > q0);
        #pragma unroll
        for (int i = 0; i < 8; ++i) {
            #pragma unroll
            for (int j = 0; j < 4; ++j) {
                float sv = sacc[i][j] * 0.125f;
                if (needmask) {
                    int qi = q0 + ty * 8 + i;
                    int kj = j0 + tx + 16 * j;
                    if (kj > qi) sv = -1e30f;
                }
                sacc[i][j] = sv;
            }
        }

        #pragma unroll
        for (int i = 0; i < 8; ++i) {
            float rm = fmaxf(fmaxf(sacc[i][0], sacc[i][1]), fmaxf(sacc[i][2], sacc[i][3]));
            #pragma unroll
            for (int d = 1; d < 16; d <<= 1)
                rm = fmaxf(rm, __shfl_xor_sync(0xffffffffu, rm, d));
            float mnew = fmaxf(m_i[i], rm);
            float corr = __expf(m_i[i] - mnew);
            float rs = 0.0f;
            #pragma unroll
            for (int j = 0; j < 4; ++j) {
                float p = __expf(sacc[i][j] - mnew);
                sP[(ty * 8 + i) * 68 + tx + 16 * j] = p;
                rs += p;
            }
            #pragma unroll
            for (int d = 1; d < 16; d <<= 1)
                rs += __shfl_xor_sync(0xffffffffu, rs, d);
            l_i[i] = l_i[i] * corr + rs;
            m_i[i] = mnew;
            #pragma unroll
            for (int j = 0; j < 4; ++j) o[i][j] *= corr;
        }
        __syncthreads();

        #pragma unroll 2
        for (int c4 = 0; c4 < 16; ++c4) {
            float pf[8][4];
            #pragma unroll
            for (int i = 0; i < 8; ++i) {
                float4 t = *(const float4*)&sP[(ty * 8 + i) * 68 + c4 * 4];
                pf[i][0] = t.x; pf[i][1] = t.y; pf[i][2] = t.z; pf[i][3] = t.w;
            }
            #pragma unroll
            for (int cc = 0; cc < 4; ++cc) {
                float vv[4];
                #pragma unroll
                for (int j = 0; j < 4; ++j)
                    vv[j] = sV[(c4 * 4 + cc) * 68 + tx + 16 * j];
                #pragma unroll
                for (int i = 0; i < 8; ++i)
                    #pragma unroll
                    for (int j = 0; j < 4; ++j)
                        o[i][j] = fmaf(pf[i][cc], vv[j], o[i][j]);
            }
        }
        __syncthreads();
    }

    const int b = bh / Hn;
    const int h = bh % Hn;
    #pragma unroll
    for (int i = 0; i < 8; ++i) {
        float inv = 1.0f / l_i[i];
        int srow = q0 + ty * 8 + i;
        size_t zb = (((size_t)b * Sn + srow) * Hn + h) * (size_t)An;
        #pragma unroll
        for (int j = 0; j < 4; ++j)
            g_z[zb + tx + 16 * j] = o[i][j] * inv;
    }
}

// ---------------------------------------------------------------------------
extern "C" void kernel_launch(void* const* d_in, const int* in_sizes, int n_in,
                              void* d_out, int out_size)
{
    const float* residual = (const float*)d_in[0];
    const float* Wq = (const float*)d_in[1];
    const float* Wk = (const float*)d_in[2];
    const float* Wv = (const float*)d_in[3];
    const float* Wo = (const float*)d_in[4];
    const float* bq = (const float*)d_in[5];
    const float* bk = (const float*)d_in[6];
    const float* bv = (const float*)d_in[7];
    const float* bo = (const float*)d_in[8];
    float* out = (float*)d_out;

    cudaFuncSetAttribute(flash_kernel, cudaFuncAttributeMaxDynamicSharedMemorySize,
                         FLASH_SMEM_BYTES);
    cudaFuncSetAttribute(gemm_mma_kernel<0>, cudaFuncAttributeMaxDynamicSharedMemorySize,
                         GEMM_SMEM);
    cudaFuncSetAttribute(gemm_mma_kernel<1>, cudaFuncAttributeMaxDynamicSharedMemorySize,
                         GEMM_SMEM);

    // 1) QKV projections (tf32 mma.sync; W used k-major in place)
    gemm_mma_kernel<0><<<dim3(HA / 128, Mrows / 128, 3), 256, GEMM_SMEM>>>(
        residual, Wq, Wk, Wv, bq, bk, bv, nullptr);

    // 2) Causal flash attention (fp32 SIMT)
    flash_kernel<<<dim3(Sn / 128, Bn * Hn), 256, FLASH_SMEM_BYTES>>>();

    // 3) Output projection (tf32 mma.sync; A = g_z via device symbol)
    gemm_mma_kernel<1><<<dim3(Dn / 128, Mrows / 128, 1), 256, GEMM_SMEM>>>(
        nullptr, Wo, nullptr, nullptr, bo, nullptr, nullptr, out);
}

// round 5
// speedup vs baseline: 3.1218x; 1.9566x over previous
#include <cuda_runtime.h>
#include <cuda_bf16.h>
#include <cstdint>

// Problem dims (fixed)
constexpr int Bn = 2;
constexpr int Sn = 2048;
constexpr int Dn = 1024;
constexpr int Hn = 16;
constexpr int An = 64;
constexpr int Mrows = Bn * Sn;        // 4096
constexpr int HA = Hn * An;           // 1024

// Scratch (device globals; allocation-free)
__device__ __align__(256) float g_q[(size_t)Bn * Hn * Sn * An];   // [B,H,S,A]
__device__ __align__(256) float g_k[(size_t)Bn * Hn * Sn * An];
__device__ __align__(256) float g_v[(size_t)Bn * Hn * Sn * An];
__device__ __align__(256) float g_z[(size_t)Bn * Sn * Hn * An];   // [B,S,H,A]

// ---------------------------------------------------------------------------
// Helpers (sm_80-baseline PTX only: cp.async + mma.sync tf32; NO tcgen05)
// ---------------------------------------------------------------------------
__device__ __forceinline__ void cp_async16(uint32_t dst, const void* src) {
    asm volatile("cp.async.cg.shared.global [%0], [%1], 16;" :: "r"(dst), "l"(src) : "memory");
}
__device__ __forceinline__ uint32_t smem_u32(const void* p) {
    uint32_t a;
    asm("{ .reg .u64 t; cvta.to.shared.u64 t, %1; cvt.u32.u64 %0, t; }" : "=r"(a) : "l"(p));
    return a;
}
__device__ __forceinline__ void cp_commit() {
    asm volatile("cp.async.commit_group;" ::: "memory");
}
template <int N>
__device__ __forceinline__ void cp_wait() {
    asm volatile("cp.async.wait_group %0;" :: "n"(N) : "memory");
}
__device__ __forceinline__ uint32_t f2tf32(float x) {
    uint32_t r;
    asm("cvt.rna.tf32.f32 %0, %1;" : "=r"(r) : "f"(x));
    return r;
}
__device__ __forceinline__ void mma_tf32_16n8k8(float* c, const uint32_t* a, const uint32_t* b) {
    asm volatile(
        "mma.sync.aligned.m16n8k8.row.col.f32.tf32.tf32.f32 "
        "{%0,%1,%2,%3}, {%4,%5,%6,%7}, {%8,%9}, {%0,%1,%2,%3};"
        : "+f"(c[0]), "+f"(c[1]), "+f"(c[2]), "+f"(c[3])
        : "r"(a[0]), "r"(a[1]), "r"(a[2]), "r"(a[3]), "r"(b[0]), "r"(b[1]));
}

// ---------------------------------------------------------------------------
// tf32 mma.sync GEMM (unchanged from R4, proven)
// ---------------------------------------------------------------------------
constexpr int LDA = 36;
constexpr int LDB = 136;
constexpr int A_STG = 128 * LDA;
constexpr int B_STG = 32 * LDB;
constexpr int STG_FLOATS = A_STG + B_STG;
constexpr int NSTAGE = 3;
constexpr int GEMM_SMEM = NSTAGE * STG_FLOATS * 4;
constexpr int KCHUNKS = 1024 / 32;

template<int MODE>
__global__ __launch_bounds__(256) void gemm_mma_kernel(
    const float* __restrict__ Ain,
    const float* __restrict__ Wq, const float* __restrict__ Wk, const float* __restrict__ Wv,
    const float* __restrict__ b0, const float* __restrict__ b1, const float* __restrict__ b2,
    float* __restrict__ outp)
{
    extern __shared__ __align__(16) float smem[];

    const int tid = threadIdx.x;
    const int lane = tid & 31;
    const int wid = tid >> 5;
    const int warp_m = wid & 1;
    const int warp_n = wid >> 1;
    const int grp = lane >> 2;
    const int qd = lane & 3;

    const int m0 = blockIdx.y * 128;
    const int n0 = blockIdx.x * 128;
    const int z = blockIdx.z;

    const float* A = (MODE == 0) ? Ain : (const float*)g_z;

    const float* W;
    const float* bias;
    if (MODE == 0) {
        W = (z == 0) ? Wq : (z == 1) ? Wk : Wv;
        bias = (z == 0) ? b0 : (z == 1) ? b1 : b2;
    } else {
        W = Wq;
        bias = b0;
    }

    const uint32_t smem_base = smem_u32(smem);

    auto produce = [&](int kc) {
        const int slot = kc % NSTAGE;
        const uint32_t sA = smem_base + (uint32_t)(slot * STG_FLOATS) * 4;
        const uint32_t sB = sA + (uint32_t)A_STG * 4;
        #pragma unroll
        for (int i = 0; i < 4; ++i) {
            int task = i * 256 + tid;
            int r = task >> 3;
            int sgm = task & 7;
            cp_async16(sA + (uint32_t)(r * LDA + sgm * 4) * 4,
                       A + (size_t)(m0 + r) * 1024 + kc * 32 + sgm * 4);
        }
        #pragma unroll
        for (int i = 0; i < 4; ++i) {
            int task = i * 256 + tid;
            int kr = task >> 5;
            int sgm = task & 31;
            int nl = sgm * 4;
            const float* src;
            if (MODE == 0) {
                int ng = n0 + nl;
                src = W + (size_t)(ng >> 6) * (Dn * An) + (size_t)(kc * 32 + kr) * An + (ng & 63);
            } else {
                src = W + (size_t)(kc * 32 + kr) * Dn + n0 + nl;
            }
            cp_async16(sB + (uint32_t)(kr * LDB + nl) * 4, src);
        }
        cp_commit();
    };

    float acc[4][4][4];
    #pragma unroll
    for (int mt = 0; mt < 4; ++mt)
        #pragma unroll
        for (int nt = 0; nt < 4; ++nt)
            #pragma unroll
            for (int e = 0; e < 4; ++e) acc[mt][nt][e] = 0.0f;

    produce(0);
    produce(1);

    for (int kc = 0; kc < KCHUNKS; ++kc) {
        cp_wait<1>();
        __syncthreads();
        if (kc + 2 < KCHUNKS) produce(kc + 2);

        const int slot = kc % NSTAGE;
        const float* sA = smem + slot * STG_FLOATS;
        const float* sB = sA + A_STG;

        #pragma unroll
        for (int ks = 0; ks < 4; ++ks) {
            uint32_t af[4][4], bf[4][2];
            #pragma unroll
            for (int mt = 0; mt < 4; ++mt) {
                const int rb = warp_m * 64 + mt * 16 + grp;
                const int cb = ks * 8 + qd;
                af[mt][0] = f2tf32(sA[rb * LDA + cb]);
                af[mt][1] = f2tf32(sA[(rb + 8) * LDA + cb]);
                af[mt][2] = f2tf32(sA[rb * LDA + cb + 4]);
                af[mt][3] = f2tf32(sA[(rb + 8) * LDA + cb + 4]);
            }
            #pragma unroll
            for (int nt = 0; nt < 4; ++nt) {
                const int nb = warp_n * 32 + nt * 8 + grp;
                bf[nt][0] = f2tf32(sB[(ks * 8 + qd) * LDB + nb]);
                bf[nt][1] = f2tf32(sB[(ks * 8 + qd + 4) * LDB + nb]);
            }
            #pragma unroll
            for (int mt = 0; mt < 4; ++mt)
                #pragma unroll
                for (int nt = 0; nt < 4; ++nt)
                    mma_tf32_16n8k8(acc[mt][nt], af[mt], bf[nt]);
        }
        __syncthreads();
    }

    #pragma unroll
    for (int mt = 0; mt < 4; ++mt) {
        #pragma unroll
        for (int half = 0; half < 2; ++half) {
            const int m = m0 + warp_m * 64 + mt * 16 + grp + half * 8;
            #pragma unroll
            for (int nt = 0; nt < 4; ++nt) {
                const int n = n0 + warp_n * 32 + nt * 8 + qd * 2;
                float2 v;
                v.x = acc[mt][nt][half * 2 + 0] + bias[n];
                v.y = acc[mt][nt][half * 2 + 1] + bias[n + 1];
                if (MODE == 0) {
                    const int b = m >> 11;
                    const int s = m & 2047;
                    float* O = (z == 0) ? g_q : (z == 1) ? g_k : g_v;
                    *(float2*)&O[(((size_t)b * Hn + (n >> 6)) * Sn + s) * An + (n & 63)] = v;
                } else {
                    *(float2*)&outp[(size_t)m * Dn + n] = v;
                }
            }
        }
    }
}

// ---------------------------------------------------------------------------
// Causal flash attention on tensor cores (mma.sync tf32).
// 256 threads = 8 warps; warp w owns q-rows [q0 + w*16, +16). BN=64 kv/tile.
// Q pre-scaled by 0.125 and tf32-converted once; fragments in registers.
// ---------------------------------------------------------------------------
constexpr int LDQ = 68;   // u32 pitch: fragment loads bank-perfect
constexpr int LDK = 68;
constexpr int LDV = 72;   // 8*qd+grp covers all 32 banks
constexpr int LDP = 68;
constexpr int FL_SQ = 128 * LDQ;                   // u32 counts
constexpr int FL_SK = 64 * LDK;
constexpr int FL_SV = 64 * LDV;
constexpr int FL_SP = 128 * LDP;
constexpr int FLASH_SMEM_BYTES = (FL_SQ + FL_SK + FL_SV + FL_SP) * 4;  // 105472

__global__ __launch_bounds__(256) void flash_mma_kernel()
{
    extern __shared__ uint32_t sm_u[];
    uint32_t* sQ = sm_u;
    uint32_t* sK = sQ + FL_SQ;
    uint32_t* sV = sK + FL_SK;
    uint32_t* sP = sV + FL_SV;

    const int tid = threadIdx.x;
    const int lane = tid & 31;
    const int wid = tid >> 5;       // 0..7
    const int grp = lane >> 2;      // 0..7
    const int qd = lane & 3;        // 0..3

    const int bh = blockIdx.y;
    const size_t base = (size_t)bh * Sn * An;
    const int q0 = blockIdx.x * 128;

    // ---- Load Q tile, scale by 1/sqrt(64), convert to tf32 ----
    for (int idx = tid; idx < 128 * 16; idx += 256) {
        int r = idx >> 4;
        int c4 = (idx & 15) * 4;
        float4 v = *(const float4*)&g_q[base + (size_t)(q0 + r) * An + c4];
        sQ[r * LDQ + c4 + 0] = f2tf32(v.x * 0.125f);
        sQ[r * LDQ + c4 + 1] = f2tf32(v.y * 0.125f);
        sQ[r * LDQ + c4 + 2] = f2tf32(v.z * 0.125f);
        sQ[r * LDQ + c4 + 3] = f2tf32(v.w * 0.125f);
    }
    __syncthreads();

    // ---- Q fragments in registers for all 8 k-steps ----
    const int r0 = wid * 16 + grp;     // warp-local row (grp) ; +8 for second
    uint32_t qf[8][4];
    #pragma unroll
    for (int ks = 0; ks < 8; ++ks) {
        qf[ks][0] = sQ[r0 * LDQ + ks * 8 + qd];
        qf[ks][1] = sQ[(r0 + 8) * LDQ + ks * 8 + qd];
        qf[ks][2] = sQ[r0 * LDQ + ks * 8 + qd + 4];
        qf[ks][3] = sQ[(r0 + 8) * LDQ + ks * 8 + qd + 4];
    }

    float m0r = -1e30f, m1r = -1e30f, l0r = 0.0f, l1r = 0.0f;
    float o[8][4];
    #pragma unroll
    for (int nt = 0; nt < 8; ++nt)
        #pragma unroll
        for (int e = 0; e < 4; ++e) o[nt][e] = 0.0f;

    const int grow0 = q0 + r0;         // global q row for c0/c1
    const int grow1 = grow0 + 8;       // for c2/c3

    for (int j0 = 0; j0 < q0 + 128; j0 += 64) {
        // ---- Fill K, V tiles (tf32) ----
        for (int idx = tid; idx < 64 * 16; idx += 256) {
            int r = idx >> 4;
            int c4 = (idx & 15) * 4;
            float4 kv4 = *(const float4*)&g_k[base + (size_t)(j0 + r) * An + c4];
            sK[r * LDK + c4 + 0] = f2tf32(kv4.x);
            sK[r * LDK + c4 + 1] = f2tf32(kv4.y);
            sK[r * LDK + c4 + 2] = f2tf32(kv4.z);
            sK[r * LDK + c4 + 3] = f2tf32(kv4.w);
            float4 vv4 = *(const float4*)&g_v[base + (size_t)(j0 + r) * An + c4];
            sV[r * LDV + c4 + 0] = f2tf32(vv4.x);
            sV[r * LDV + c4 + 1] = f2tf32(vv4.y);
            sV[r * LDV + c4 + 2] = f2tf32(vv4.z);
            sV[r * LDV + c4 + 3] = f2tf32(vv4.w);
        }
        __syncthreads();

        // ---- S = Q @ K^T  (rows: warp tile 16, cols: 64 kv) ----
        float sacc[8][4];
        #pragma unroll
        for (int nt = 0; nt < 8; ++nt)
            #pragma unroll
            for (int e = 0; e < 4; ++e) sacc[nt][e] = 0.0f;

        #pragma unroll
        for (int ks = 0; ks < 8; ++ks) {
            uint32_t kf[8][2];
            #pragma unroll
            for (int nt = 0; nt < 8; ++nt) {
                kf[nt][0] = sK[(nt * 8 + grp) * LDK + ks * 8 + qd];
                kf[nt][1] = sK[(nt * 8 + grp) * LDK + ks * 8 + qd + 4];
            }
            #pragma unroll
            for (int nt = 0; nt < 8; ++nt)
                mma_tf32_16n8k8(sacc[nt], qf[ks], kf[nt]);
        }

        // ---- causal mask ----
        const bool needmask = (j0 + 63 > grow0 - grp + 0) || true; // cheap: compute per element below
        if (j0 + 63 > q0) {
            #pragma unroll
            for (int nt = 0; nt < 8; ++nt) {
                int c = j0 + nt * 8 + qd * 2;
                if (c > grow0)     sacc[nt][0] = -1e30f;
                if (c + 1 > grow0) sacc[nt][1] = -1e30f;
                if (c > grow1)     sacc[nt][2] = -1e30f;
                if (c + 1 > grow1) sacc[nt][3] = -1e30f;
            }
        }
        (void)needmask;

        // ---- online softmax on fragments (row in one quad: shfl 1,2) ----
        float rm0 = -1e30f, rm1 = -1e30f;
        #pragma unroll
        for (int nt = 0; nt < 8; ++nt) {
            rm0 = fmaxf(rm0, fmaxf(sacc[nt][0], sacc[nt][1]));
            rm1 = fmaxf(rm1, fmaxf(sacc[nt][2], sacc[nt][3]));
        }
        rm0 = fmaxf(rm0, __shfl_xor_sync(0xffffffffu, rm0, 1));
        rm0 = fmaxf(rm0, __shfl_xor_sync(0xffffffffu, rm0, 2));
        rm1 = fmaxf(rm1, __shfl_xor_sync(0xffffffffu, rm1, 1));
        rm1 = fmaxf(rm1, __shfl_xor_sync(0xffffffffu, rm1, 2));

        float mn0 = fmaxf(m0r, rm0);
        float mn1 = fmaxf(m1r, rm1);
        float corr0 = __expf(m0r - mn0);
        float corr1 = __expf(m1r - mn1);
        m0r = mn0; m1r = mn1;

        float rs0 = 0.0f, rs1 = 0.0f;
        #pragma unroll
        for (int nt = 0; nt < 8; ++nt) {
            float p0 = __expf(sacc[nt][0] - mn0);
            float p1 = __expf(sacc[nt][1] - mn0);
            float p2 = __expf(sacc[nt][2] - mn1);
            float p3 = __expf(sacc[nt][3] - mn1);
            rs0 += p0 + p1;
            rs1 += p2 + p3;
            const int pc = nt * 8 + qd * 2;
            sP[r0 * LDP + pc] = f2tf32(p0);
            sP[r0 * LDP + pc + 1] = f2tf32(p1);
            sP[(r0 + 8) * LDP + pc] = f2tf32(p2);
            sP[(r0 + 8) * LDP + pc + 1] = f2tf32(p3);
        }
        rs0 += __shfl_xor_sync(0xffffffffu, rs0, 1);
        rs0 += __shfl_xor_sync(0xffffffffu, rs0, 2);
        rs1 += __shfl_xor_sync(0xffffffffu, rs1, 1);
        rs1 += __shfl_xor_sync(0xffffffffu, rs1, 2);
        l0r = l0r * corr0 + rs0;
        l1r = l1r * corr1 + rs1;

        #pragma unroll
        for (int nt = 0; nt < 8; ++nt) {
            o[nt][0] *= corr0;
            o[nt][1] *= corr0;
            o[nt][2] *= corr1;
            o[nt][3] *= corr1;
        }
        __syncwarp();   // P rows are warp-private; order STS before LDS

        // ---- O += P @ V ----
        #pragma unroll
        for (int ks = 0; ks < 8; ++ks) {
            uint32_t af[4];
            af[0] = sP[r0 * LDP + ks * 8 + qd];
            af[1] = sP[(r0 + 8) * LDP + ks * 8 + qd];
            af[2] = sP[r0 * LDP + ks * 8 + qd + 4];
            af[3] = sP[(r0 + 8) * LDP + ks * 8 + qd + 4];
            #pragma unroll
            for (int nt = 0; nt < 8; ++nt) {
                uint32_t bf[2];
                bf[0] = sV[(ks * 8 + qd) * LDV + nt * 8 + grp];
                bf[1] = sV[(ks * 8 + qd + 4) * LDV + nt * 8 + grp];
                mma_tf32_16n8k8(o[nt], af, bf);
            }
        }
        __syncthreads();   // K/V consumed by all warps before next fill
    }

    // ---- epilogue: z[b,s,h,a] = o / l ----
    const int b = bh >> 4;
    const int h = bh & 15;
    const float inv0 = 1.0f / l0r;
    const float inv1 = 1.0f / l1r;
    #pragma unroll
    for (int nt = 0; nt < 8; ++nt) {
        const int a = nt * 8 + qd * 2;
        float2 v0, v1;
        v0.x = o[nt][0] * inv0;
        v0.y = o[nt][1] * inv0;
        v1.x = o[nt][2] * inv1;
        v1.y = o[nt][3] * inv1;
        *(float2*)&g_z[(((size_t)b * Sn + grow0) * Hn + h) * An + a] = v0;
        *(float2*)&g_z[(((size_t)b * Sn + grow1) * Hn + h) * An + a] = v1;
    }
}

// ---------------------------------------------------------------------------
extern "C" void kernel_launch(void* const* d_in, const int* in_sizes, int n_in,
                              void* d_out, int out_size)
{
    const float* residual = (const float*)d_in[0];
    const float* Wq = (const float*)d_in[1];
    const float* Wk = (const float*)d_in[2];
    const float* Wv = (const float*)d_in[3];
    const float* Wo = (const float*)d_in[4];
    const float* bq = (const float*)d_in[5];
    const float* bk = (const float*)d_in[6];
    const float* bv = (const float*)d_in[7];
    const float* bo = (const float*)d_in[8];
    float* out = (float*)d_out;

    cudaFuncSetAttribute(flash_mma_kernel, cudaFuncAttributeMaxDynamicSharedMemorySize,
                         FLASH_SMEM_BYTES);
    cudaFuncSetAttribute(gemm_mma_kernel<0>, cudaFuncAttributeMaxDynamicSharedMemorySize,
                         GEMM_SMEM);
    cudaFuncSetAttribute(gemm_mma_kernel<1>, cudaFuncAttributeMaxDynamicSharedMemorySize,
                         GEMM_SMEM);

    // 1) QKV projections (tf32 mma.sync)
    gemm_mma_kernel<0><<<dim3(HA / 128, Mrows / 128, 3), 256, GEMM_SMEM>>>(
        residual, Wq, Wk, Wv, bq, bk, bv, nullptr);

    // 2) Causal flash attention (tf32 mma.sync)
    flash_mma_kernel<<<dim3(Sn / 128, Bn * Hn), 256, FLASH_SMEM_BYTES>>>();

    // 3) Output projection (tf32 mma.sync; A = g_z via device symbol)
    gemm_mma_kernel<1><<<dim3(Dn / 128, Mrows / 128, 1), 256, GEMM_SMEM>>>(
        nullptr, Wo, nullptr, nullptr, bo, nullptr, nullptr, out);
}